// round 1
// baseline (speedup 1.0000x reference)
#include <cuda_runtime.h>
#include <math.h>

#define NV      6890
#define NPTS    16384
#define SPLIT   4
#define KRANGE  1723     // ceil(6890/4)
#define LDF     704      // padded feature leading dim (700 -> 704)

// ---------------- scratch (device globals; no allocations allowed) ----------
__device__ float              g_feat[(size_t)NPTS * LDF];   // 46 MB
__device__ float              g_h1[(size_t)NPTS * 256];
__device__ float              g_h2[(size_t)NPTS * 256];
__device__ float              g_Rinv[NV * 9];
__device__ int                g_knn[NPTS];
__device__ unsigned long long g_part[SPLIT * NPTS];

// ---------------- accurate sincos (robust even under --use_fast_math) -------
__device__ __forceinline__ void sincos_acc(float x, float* s, float* c) {
    double xd = (double)x;
    double q  = rint(xd * 0.15915494309189535);   // 1/(2*pi)
    double r  = xd - q * 6.283185307179586;       // |r| <= pi
    float  rf = (float)r;
    sincosf(rf, s, c);
}

// ---------------- kernel 1: per-vertex inverse of 4x4, keep top-left 3x3 ----
__global__ void invert_kernel(const float* __restrict__ trans) {
    int v = blockIdx.x * blockDim.x + threadIdx.x;
    if (v >= NV) return;
    float m[16];
#pragma unroll
    for (int k = 0; k < 16; k++) m[k] = trans[k * NV + v];   // trans[(i*4+j)*NV + v]

    // adjugate cofactors (rows 0..2 of inverse + inv12 for det) — layout-symmetric
    float i0  =  m[5]*m[10]*m[15] - m[5]*m[11]*m[14] - m[9]*m[6]*m[15] + m[9]*m[7]*m[14] + m[13]*m[6]*m[11] - m[13]*m[7]*m[10];
    float i4  = -m[4]*m[10]*m[15] + m[4]*m[11]*m[14] + m[8]*m[6]*m[15] - m[8]*m[7]*m[14] - m[12]*m[6]*m[11] + m[12]*m[7]*m[10];
    float i8  =  m[4]*m[9]*m[15]  - m[4]*m[11]*m[13] - m[8]*m[5]*m[15] + m[8]*m[7]*m[13] + m[12]*m[5]*m[11] - m[12]*m[7]*m[9];
    float i12 = -m[4]*m[9]*m[14]  + m[4]*m[10]*m[13] + m[8]*m[5]*m[14] - m[8]*m[6]*m[13] - m[12]*m[5]*m[10] + m[12]*m[6]*m[9];
    float i1  = -m[1]*m[10]*m[15] + m[1]*m[11]*m[14] + m[9]*m[2]*m[15] - m[9]*m[3]*m[14] - m[13]*m[2]*m[11] + m[13]*m[3]*m[10];
    float i5  =  m[0]*m[10]*m[15] - m[0]*m[11]*m[14] - m[8]*m[2]*m[15] + m[8]*m[3]*m[14] + m[12]*m[2]*m[11] - m[12]*m[3]*m[10];
    float i9  = -m[0]*m[9]*m[15]  + m[0]*m[11]*m[13] + m[8]*m[1]*m[15] - m[8]*m[3]*m[13] - m[12]*m[1]*m[11] + m[12]*m[3]*m[9];
    float i2  =  m[1]*m[6]*m[15]  - m[1]*m[7]*m[14]  - m[5]*m[2]*m[15] + m[5]*m[3]*m[14] + m[13]*m[2]*m[7]  - m[13]*m[3]*m[6];
    float i6  = -m[0]*m[6]*m[15]  + m[0]*m[7]*m[14]  + m[4]*m[2]*m[15] - m[4]*m[3]*m[14] - m[12]*m[2]*m[7]  + m[12]*m[3]*m[6];
    float i10 =  m[0]*m[5]*m[15]  - m[0]*m[7]*m[13]  - m[4]*m[1]*m[15] + m[4]*m[3]*m[13] + m[12]*m[1]*m[7]  - m[12]*m[3]*m[5];

    float det = m[0]*i0 + m[1]*i4 + m[2]*i8 + m[3]*i12;
    float id  = 1.0f / det;
    float* R = g_Rinv + v * 9;
    R[0] = i0*id;  R[1] = i1*id;  R[2] = i2*id;     // inv row 0, cols 0..2
    R[3] = i4*id;  R[4] = i5*id;  R[5] = i6*id;     // inv row 1
    R[6] = i8*id;  R[7] = i9*id;  R[8] = i10*id;    // inv row 2
}

// ---------------- kernel 2: KNN, 4-way keypoint split ------------------------
__global__ __launch_bounds__(256) void knn_kernel(const float* __restrict__ pts,
                                                  const float* __restrict__ kp) {
    __shared__ float4 sk[KRANGE];
    int pt = blockIdx.x * 256 + threadIdx.x;
    int ks = blockIdx.y * KRANGE;
    int ke = min(ks + KRANGE, NV);
    int n  = ke - ks;

    for (int i = threadIdx.x; i < n; i += 256) {
        int vv = ks + i;
        float kx = kp[vv*3], ky = kp[vv*3+1], kz = kp[vv*3+2];
        sk[i] = make_float4(kx, ky, kz, -0.5f*(kx*kx + ky*ky + kz*kz));
    }
    __syncthreads();

    float px = pts[pt*6], py = pts[pt*6+1], pz = pts[pt*6+2];
    float best = -1e30f; int bi = ks;

    int i = 0;
#pragma unroll 1
    for (; i + 4 <= n; i += 4) {
#pragma unroll
        for (int u = 0; u < 4; u++) {
            float4 k = sk[i+u];
            float s = fmaf(px, k.x, fmaf(py, k.y, fmaf(pz, k.z, k.w)));
            if (s > best) { best = s; bi = ks + i + u; }
        }
    }
    for (; i < n; i++) {
        float4 k = sk[i];
        float s = fmaf(px, k.x, fmaf(py, k.y, fmaf(pz, k.z, k.w)));
        if (s > best) { best = s; bi = ks + i; }
    }
    // pack (minimize -best, ties -> lowest index)
    float mneg = -best;
    unsigned int ub = __float_as_uint(mneg);
    ub = (ub & 0x80000000u) ? ~ub : (ub | 0x80000000u);
    g_part[blockIdx.y * NPTS + pt] = ((unsigned long long)ub << 32) | (unsigned int)bi;
}

__global__ void knn_reduce() {
    int pt = blockIdx.x * blockDim.x + threadIdx.x;
    if (pt >= NPTS) return;
    unsigned long long b = g_part[pt];
#pragma unroll
    for (int s = 1; s < SPLIT; s++) {
        unsigned long long o = g_part[s * NPTS + pt];
        if (o < b) b = o;
    }
    g_knn[pt] = (int)(b & 0xFFFFFFFFull);
}

// ---------------- kernel 3: feature build + direction posenc (warp/point) ---
__global__ __launch_bounds__(256) void feat_kernel(const float* __restrict__ pts,
                                                   const float* __restrict__ kp,
                                                   const int*   __restrict__ nbr,
                                                   const float* __restrict__ rest,
                                                   const float* __restrict__ lat,
                                                   float*       __restrict__ out) {
    int gw   = (blockIdx.x * blockDim.x + threadIdx.x) >> 5;
    int lane = threadIdx.x & 31;
    if (gw >= NPTS) return;

    float px = pts[gw*6], py = pts[gw*6+1], pz = pts[gw*6+2];
    int kidx = g_knn[gw];

    int vj = (lane < 7) ? nbr[kidx*7 + lane] : 0;
    int j  = (lane < 21) ? (lane / 3) : ((lane < 28) ? (lane - 21) : 0);
    int v  = __shfl_sync(0xffffffffu, vj, j);

    float vf = 0.0f;
    if (lane < 21) {
        vf = rest[v*3 + (lane % 3)];
    } else if (lane < 28) {
        float dx = px - kp[v*3], dy = py - kp[v*3+1], dz = pz - kp[v*3+2];
        vf = sqrtf(dx*dx + dy*dy + dz*dz);
    }

    float* Fp = g_feat + (size_t)gw * LDF;
    if (lane < 28) {
        Fp[lane] = vf;
        float freq = 1.0f;
#pragma unroll
        for (int k = 0; k < 10; k++) {
            float s, c;
            sincos_acc(vf * freq, &s, &c);
            Fp[28  + k*28 + lane] = s;
            Fp[308 + k*28 + lane] = c;
            freq *= 2.0f;
        }
    }
    if (lane < 4) Fp[700 + lane] = 0.0f;   // zero pad cols 700..703

    // latent: 112 values
#pragma unroll
    for (int it = 0; it < 4; it++) {
        int l  = it * 32 + lane;
        int jj = (l < 112) ? (l >> 4) : 0;
        int vv = __shfl_sync(0xffffffffu, vj, jj);
        if (l < 112) Fp[588 + l] = lat[vv*16 + (l & 15)];
    }

    // direction + posenc(direction, 4) -> out[pt*283 + 256 .. 282]
    if (lane == 0) {
        float dx = px - kp[kidx*3], dy = py - kp[kidx*3+1], dz = pz - kp[kidx*3+2];
        const float* R = g_Rinv + kidx * 9;
        float d0 = R[0]*dx + R[1]*dy + R[2]*dz;
        float d1 = R[3]*dx + R[4]*dy + R[5]*dz;
        float d2 = R[6]*dx + R[7]*dy + R[8]*dz;
        float nn = sqrtf(d0*d0 + d1*d1 + d2*d2);
        float iv = 1.0f / fmaxf(nn, 1e-12f);
        d0 *= iv; d1 *= iv; d2 *= iv;
        float* op = out + (size_t)gw * 283 + 256;
        op[0] = d0; op[1] = d1; op[2] = d2;
        float dir[3] = {d0, d1, d2};
        float freq = 1.0f;
#pragma unroll
        for (int k = 0; k < 4; k++) {
#pragma unroll
            for (int c = 0; c < 3; c++) {
                float s, cc;
                sincos_acc(dir[c] * freq, &s, &cc);
                op[3  + k*3 + c] = s;
                op[15 + k*3 + c] = cc;
            }
            freq *= 2.0f;
        }
    }
}

// ---------------- kernel 4: tiled fp32 GEMM + bias (+ReLU) ------------------
// C[M,N](ldc) = act(A[M,K](lda) @ B[K,N](ldb=N) + bias)
#define BM 128
#define BN 128
#define BK 16

template <bool RELU>
__global__ __launch_bounds__(256) void gemm_bias(const float* __restrict__ A, int lda,
                                                 const float* __restrict__ B,
                                                 const float* __restrict__ bias,
                                                 float* __restrict__ C, int ldc,
                                                 int M, int N, int K) {
    __shared__ float As[BK][BM];
    __shared__ float Bs[BK][BN];

    int t  = threadIdx.x;
    int m0 = blockIdx.x * BM;
    int n0 = blockIdx.y * BN;
    int tx = t & 15, ty = t >> 4;

    float acc[8][8];
#pragma unroll
    for (int i = 0; i < 8; i++)
#pragma unroll
        for (int jq = 0; jq < 8; jq++) acc[i][jq] = 0.0f;

    int ktiles = (K + BK - 1) / BK;
    for (int kt = 0; kt < ktiles; kt++) {
        int k0 = kt * BK;
        // global -> regs
        float4 aR[2], bR[2];
#pragma unroll
        for (int i = 0; i < 2; i++) {
            int f    = t + i * 256;            // 0..511
            int arow = f >> 2, ac4 = f & 3;
            aR[i] = *reinterpret_cast<const float4*>(&A[(size_t)(m0 + arow) * lda + k0 + ac4 * 4]);
            int brow = f >> 5, bcol = (f & 31) * 4;
            if (k0 + brow < K)
                bR[i] = *reinterpret_cast<const float4*>(&B[(size_t)(k0 + brow) * N + n0 + bcol]);
            else
                bR[i] = make_float4(0.f, 0.f, 0.f, 0.f);
        }
        __syncthreads();
        // regs -> smem (A transposed)
#pragma unroll
        for (int i = 0; i < 2; i++) {
            int f    = t + i * 256;
            int arow = f >> 2, ac4 = f & 3;
            As[ac4*4 + 0][arow] = aR[i].x;
            As[ac4*4 + 1][arow] = aR[i].y;
            As[ac4*4 + 2][arow] = aR[i].z;
            As[ac4*4 + 3][arow] = aR[i].w;
            int brow = f >> 5, bcol = (f & 31) * 4;
            *reinterpret_cast<float4*>(&Bs[brow][bcol]) = bR[i];
        }
        __syncthreads();
#pragma unroll
        for (int kk = 0; kk < BK; kk++) {
            float a[8], b[8];
            *reinterpret_cast<float4*>(&a[0]) = *reinterpret_cast<const float4*>(&As[kk][ty*8]);
            *reinterpret_cast<float4*>(&a[4]) = *reinterpret_cast<const float4*>(&As[kk][ty*8 + 4]);
            *reinterpret_cast<float4*>(&b[0]) = *reinterpret_cast<const float4*>(&Bs[kk][tx*8]);
            *reinterpret_cast<float4*>(&b[4]) = *reinterpret_cast<const float4*>(&Bs[kk][tx*8 + 4]);
#pragma unroll
            for (int i = 0; i < 8; i++)
#pragma unroll
                for (int jq = 0; jq < 8; jq++)
                    acc[i][jq] = fmaf(a[i], b[jq], acc[i][jq]);
        }
    }

#pragma unroll
    for (int i = 0; i < 8; i++) {
        int m = m0 + ty * 8 + i;
#pragma unroll
        for (int jq = 0; jq < 8; jq++) {
            int n = n0 + tx * 8 + jq;
            float cv = acc[i][jq] + bias[n];
            if (RELU) cv = fmaxf(cv, 0.0f);
            C[(size_t)m * ldc + n] = cv;
        }
    }
}

// ---------------- launch -----------------------------------------------------
extern "C" void kernel_launch(void* const* d_in, const int* in_sizes, int n_in,
                              void* d_out, int out_size) {
    const float* pts   = (const float*)d_in[0];
    const float* kp    = (const float*)d_in[1];
    const float* trans = (const float*)d_in[2];
    const int*   nbr   = (const int*)  d_in[3];
    const float* rest  = (const float*)d_in[4];
    const float* lat   = (const float*)d_in[5];
    const float* W1    = (const float*)d_in[6];
    const float* b1    = (const float*)d_in[7];
    const float* W2    = (const float*)d_in[8];
    const float* b2    = (const float*)d_in[9];
    const float* W3    = (const float*)d_in[10];
    const float* b3    = (const float*)d_in[11];
    float*       out   = (float*)d_out;

    void *pF, *pH1, *pH2;
    cudaGetSymbolAddress(&pF,  g_feat);
    cudaGetSymbolAddress(&pH1, g_h1);
    cudaGetSymbolAddress(&pH2, g_h2);
    float* F  = (float*)pF;
    float* H1 = (float*)pH1;
    float* H2 = (float*)pH2;

    invert_kernel<<<(NV + 127) / 128, 128>>>(trans);
    knn_kernel<<<dim3(NPTS / 256, SPLIT), 256>>>(pts, kp);
    knn_reduce<<<NPTS / 256, 256>>>();
    feat_kernel<<<NPTS / 8, 256>>>(pts, kp, nbr, rest, lat, out);

    gemm_bias<true ><<<dim3(NPTS / BM, 256 / BN), 256>>>(F,  LDF, W1, b1, H1,  256, NPTS, 256, 700);
    gemm_bias<true ><<<dim3(NPTS / BM, 256 / BN), 256>>>(H1, 256, W2, b2, H2,  256, NPTS, 256, 256);
    gemm_bias<false><<<dim3(NPTS / BM, 256 / BN), 256>>>(H2, 256, W3, b3, out, 283, NPTS, 256, 256);
}

// round 3
// speedup vs baseline: 2.6735x; 2.6735x over previous
#include <cuda_runtime.h>
#include <cstdint>
#include <math.h>

#define NV      6890
#define NPTS    16384
#define SPLIT   4
#define KRANGE  1723     // ceil(6890/4)
#define LDF     704      // padded feature leading dim (700 -> 704)

// ---------------- scratch (device globals; no allocations allowed) ----------
__device__ float              g_feat[(size_t)NPTS * LDF];   // 46 MB
__device__ float              g_h1[(size_t)NPTS * 256];
__device__ float              g_h2[(size_t)NPTS * 256];
__device__ float              g_W1h[(size_t)256 * LDF];     // W1^T hi (tf32 bits as fp32)
__device__ float              g_W1l[(size_t)256 * LDF];     // W1^T lo
__device__ float              g_W2h[(size_t)256 * 256];
__device__ float              g_W2l[(size_t)256 * 256];
__device__ float              g_W3h[(size_t)256 * 256];
__device__ float              g_W3l[(size_t)256 * 256];
__device__ float              g_Rinv[NV * 9];
__device__ int                g_knn[NPTS];
__device__ unsigned long long g_part[SPLIT * NPTS];

// ======================= small PTX helpers ===================================
__device__ __forceinline__ uint32_t smem_u32(const void* p) {
    uint32_t a;
    asm("{ .reg .u64 t; cvta.to.shared.u64 t, %1; cvt.u32.u64 %0, t; }" : "=r"(a) : "l"(p));
    return a;
}
__device__ __forceinline__ uint32_t f2tf(float x) {
    uint32_t r;
    asm("cvt.rna.tf32.f32 %0, %1;" : "=r"(r) : "f"(x));
    return r;
}
__device__ __forceinline__ void cpa16(uint32_t dst, const void* src) {
    asm volatile("cp.async.cg.shared.global [%0], [%1], 16;" :: "r"(dst), "l"(src));
}
#define CPA_COMMIT() asm volatile("cp.async.commit_group;" ::: "memory")

__device__ __forceinline__ void mma_tf32(float* c, const uint32_t* a, uint32_t b0, uint32_t b1) {
    asm volatile(
        "mma.sync.aligned.m16n8k8.row.col.f32.tf32.tf32.f32 "
        "{%0,%1,%2,%3}, {%4,%5,%6,%7}, {%8,%9}, {%0,%1,%2,%3};"
        : "+f"(c[0]), "+f"(c[1]), "+f"(c[2]), "+f"(c[3])
        : "r"(a[0]), "r"(a[1]), "r"(a[2]), "r"(a[3]), "r"(b0), "r"(b1));
}

// ---------------- accurate-enough fp32 sincos (no FP64) ---------------------
__device__ __forceinline__ void sincos_acc(float x, float* s, float* c) {
    const float C1 = 6.28125f;
    const float C2 = (float)1.9353071795864769e-3;
    const float C3 = (float)(6.283185307179586476925286766559 - 6.28125 -
                             (double)((float)1.9353071795864769e-3));
    float q = rintf(x * 0.15915494309189535f);
    float r = fmaf(q, -C1, x);
    r = fmaf(q, -C2, r);
    r = fmaf(q, -C3, r);
    sincosf(r, s, c);
}

// ---------------- kernel 1: per-vertex inverse of 4x4, keep top-left 3x3 ----
__global__ void invert_kernel(const float* __restrict__ trans) {
    int v = blockIdx.x * blockDim.x + threadIdx.x;
    if (v >= NV) return;
    float m[16];
#pragma unroll
    for (int k = 0; k < 16; k++) m[k] = trans[k * NV + v];

    float i0  =  m[5]*m[10]*m[15] - m[5]*m[11]*m[14] - m[9]*m[6]*m[15] + m[9]*m[7]*m[14] + m[13]*m[6]*m[11] - m[13]*m[7]*m[10];
    float i4  = -m[4]*m[10]*m[15] + m[4]*m[11]*m[14] + m[8]*m[6]*m[15] - m[8]*m[7]*m[14] - m[12]*m[6]*m[11] + m[12]*m[7]*m[10];
    float i8  =  m[4]*m[9]*m[15]  - m[4]*m[11]*m[13] - m[8]*m[5]*m[15] + m[8]*m[7]*m[13] + m[12]*m[5]*m[11] - m[12]*m[7]*m[9];
    float i12 = -m[4]*m[9]*m[14]  + m[4]*m[10]*m[13] + m[8]*m[5]*m[14] - m[8]*m[6]*m[13] - m[12]*m[5]*m[10] + m[12]*m[6]*m[9];
    float i1  = -m[1]*m[10]*m[15] + m[1]*m[11]*m[14] + m[9]*m[2]*m[15] - m[9]*m[3]*m[14] - m[13]*m[2]*m[11] + m[13]*m[3]*m[10];
    float i5  =  m[0]*m[10]*m[15] - m[0]*m[11]*m[14] - m[8]*m[2]*m[15] + m[8]*m[3]*m[14] + m[12]*m[2]*m[11] - m[12]*m[3]*m[10];
    float i9  = -m[0]*m[9]*m[15]  + m[0]*m[11]*m[13] + m[8]*m[1]*m[15] - m[8]*m[3]*m[13] - m[12]*m[1]*m[11] + m[12]*m[3]*m[9];
    float i2  =  m[1]*m[6]*m[15]  - m[1]*m[7]*m[14]  - m[5]*m[2]*m[15] + m[5]*m[3]*m[14] + m[13]*m[2]*m[7]  - m[13]*m[3]*m[6];
    float i6  = -m[0]*m[6]*m[15]  + m[0]*m[7]*m[14]  + m[4]*m[2]*m[15] - m[4]*m[3]*m[14] - m[12]*m[2]*m[7]  + m[12]*m[3]*m[6];
    float i10 =  m[0]*m[5]*m[15]  - m[0]*m[7]*m[13]  - m[4]*m[1]*m[15] + m[4]*m[3]*m[13] + m[12]*m[1]*m[7]  - m[12]*m[3]*m[5];

    float det = m[0]*i0 + m[1]*i4 + m[2]*i8 + m[3]*i12;
    float id  = 1.0f / det;
    float* R = g_Rinv + v * 9;
    R[0] = i0*id;  R[1] = i1*id;  R[2] = i2*id;
    R[3] = i4*id;  R[4] = i5*id;  R[5] = i6*id;
    R[6] = i8*id;  R[7] = i9*id;  R[8] = i10*id;
}

// ---------------- kernel 2: KNN, 4-way keypoint split ------------------------
__global__ __launch_bounds__(256) void knn_kernel(const float* __restrict__ pts,
                                                  const float* __restrict__ kp) {
    __shared__ float4 sk[KRANGE];
    int pt = blockIdx.x * 256 + threadIdx.x;
    int ks = blockIdx.y * KRANGE;
    int ke = min(ks + KRANGE, NV);
    int n  = ke - ks;

    for (int i = threadIdx.x; i < n; i += 256) {
        int vv = ks + i;
        float kx = kp[vv*3], ky = kp[vv*3+1], kz = kp[vv*3+2];
        sk[i] = make_float4(kx, ky, kz, -0.5f*(kx*kx + ky*ky + kz*kz));
    }
    __syncthreads();

    float px = pts[pt*6], py = pts[pt*6+1], pz = pts[pt*6+2];
    float best = -1e30f; int bi = ks;

    int i = 0;
#pragma unroll 1
    for (; i + 4 <= n; i += 4) {
#pragma unroll
        for (int u = 0; u < 4; u++) {
            float4 k = sk[i+u];
            float s = fmaf(px, k.x, fmaf(py, k.y, fmaf(pz, k.z, k.w)));
            if (s > best) { best = s; bi = ks + i + u; }
        }
    }
    for (; i < n; i++) {
        float4 k = sk[i];
        float s = fmaf(px, k.x, fmaf(py, k.y, fmaf(pz, k.z, k.w)));
        if (s > best) { best = s; bi = ks + i; }
    }
    float mneg = -best;
    unsigned int ub = __float_as_uint(mneg);
    ub = (ub & 0x80000000u) ? ~ub : (ub | 0x80000000u);
    g_part[blockIdx.y * NPTS + pt] = ((unsigned long long)ub << 32) | (unsigned int)bi;
}

__global__ void knn_reduce() {
    int pt = blockIdx.x * blockDim.x + threadIdx.x;
    if (pt >= NPTS) return;
    unsigned long long b = g_part[pt];
#pragma unroll
    for (int s = 1; s < SPLIT; s++) {
        unsigned long long o = g_part[s * NPTS + pt];
        if (o < b) b = o;
    }
    g_knn[pt] = (int)(b & 0xFFFFFFFFull);
}

// ---------------- kernel 3: feature build + direction posenc (warp/point) ---
__global__ __launch_bounds__(256) void feat_kernel(const float* __restrict__ pts,
                                                   const float* __restrict__ kp,
                                                   const int*   __restrict__ nbr,
                                                   const float* __restrict__ rest,
                                                   const float* __restrict__ lat,
                                                   float*       __restrict__ out) {
    int gw   = (blockIdx.x * blockDim.x + threadIdx.x) >> 5;
    int lane = threadIdx.x & 31;
    if (gw >= NPTS) return;

    float px = pts[gw*6], py = pts[gw*6+1], pz = pts[gw*6+2];
    int kidx = g_knn[gw];

    int vj = (lane < 7) ? nbr[kidx*7 + lane] : 0;
    int j  = (lane < 21) ? (lane / 3) : ((lane < 28) ? (lane - 21) : 0);
    int v  = __shfl_sync(0xffffffffu, vj, j);

    float vf = 0.0f;
    if (lane < 21) {
        vf = rest[v*3 + (lane % 3)];
    } else if (lane < 28) {
        float dx = px - kp[v*3], dy = py - kp[v*3+1], dz = pz - kp[v*3+2];
        vf = sqrtf(dx*dx + dy*dy + dz*dz);
    }

    float* Fp = g_feat + (size_t)gw * LDF;
    if (lane < 28) {
        Fp[lane] = vf;
        float freq = 1.0f;
#pragma unroll
        for (int k = 0; k < 10; k++) {
            float s, c;
            sincos_acc(vf * freq, &s, &c);
            Fp[28  + k*28 + lane] = s;
            Fp[308 + k*28 + lane] = c;
            freq *= 2.0f;
        }
    }
    if (lane < 4) Fp[700 + lane] = 0.0f;   // zero pad cols 700..703

#pragma unroll
    for (int it = 0; it < 4; it++) {
        int l  = it * 32 + lane;
        int jj = (l < 112) ? (l >> 4) : 0;
        int vv = __shfl_sync(0xffffffffu, vj, jj);
        if (l < 112) Fp[588 + l] = lat[vv*16 + (l & 15)];
    }

    if (lane == 0) {
        float dx = px - kp[kidx*3], dy = py - kp[kidx*3+1], dz = pz - kp[kidx*3+2];
        const float* R = g_Rinv + kidx * 9;
        float d0 = R[0]*dx + R[1]*dy + R[2]*dz;
        float d1 = R[3]*dx + R[4]*dy + R[5]*dz;
        float d2 = R[6]*dx + R[7]*dy + R[8]*dz;
        float nn = sqrtf(d0*d0 + d1*d1 + d2*d2);
        float iv = 1.0f / fmaxf(nn, 1e-12f);
        d0 *= iv; d1 *= iv; d2 *= iv;
        float* op = out + (size_t)gw * 283 + 256;
        op[0] = d0; op[1] = d1; op[2] = d2;
        float dir[3] = {d0, d1, d2};
        float freq = 1.0f;
#pragma unroll
        for (int k = 0; k < 4; k++) {
#pragma unroll
            for (int c = 0; c < 3; c++) {
                float s, cc;
                sincos_acc(dir[c] * freq, &s, &cc);
                op[3  + k*3 + c] = s;
                op[15 + k*3 + c] = cc;
            }
            freq *= 2.0f;
        }
    }
}

// ---------- weight transpose + tf32 hi/lo split: W[K][256] -> Wh/Wl[256][ldk]
__global__ void transpose_split(const float* __restrict__ W, int K,
                                float* __restrict__ Wh, float* __restrict__ Wl, int ldk) {
    __shared__ float tile[32][33];
    int kb = blockIdx.x * 32;
    int nb = blockIdx.y * 32;
    int tx = threadIdx.x, ty = threadIdx.y;   // 32 x 8
#pragma unroll
    for (int i = 0; i < 4; i++) {
        int k = kb + ty + i * 8;
        tile[ty + i * 8][tx] = (k < K) ? W[(size_t)k * 256 + nb + tx] : 0.0f;
    }
    __syncthreads();
#pragma unroll
    for (int i = 0; i < 4; i++) {
        int n = nb + ty + i * 8;
        float v = tile[tx][ty + i * 8];
        uint32_t hi = f2tf(v);
        float    lo = v - __uint_as_float(hi);
        Wh[(size_t)n * ldk + kb + tx] = __uint_as_float(hi);
        Wl[(size_t)n * ldk + kb + tx] = __uint_as_float(f2tf(lo));
    }
}

// ---------------- kernel 4: mma.sync tf32 3x-split GEMM ---------------------
// C[M,256] = act(A[M,K] @ Wt[256,K]^T + bias), CTA tile 128x128, 8 warps 4x2.
// smem per buffer: A[128][36], Bh[128][36], Bl[128][36] (pad 36 -> conflict-free
// fragment lds: bank = (4g+t) mod 32, all lanes distinct).
#define PAD      36
#define TILE_F   (128 * PAD)                 // floats per tile
#define BUF_F    (3 * TILE_F)                // A,Bh,Bl
#define GEMM_SMEM (2 * BUF_F * 4)            // 110592 bytes

template <bool RELU>
__global__ __launch_bounds__(256, 1) void gemm_mma(const float* __restrict__ A, int lda,
                                                   const float* __restrict__ Bh,
                                                   const float* __restrict__ Bl, int ldk,
                                                   const float* __restrict__ bias,
                                                   float* __restrict__ C, int ldc,
                                                   int kchunks) {
    extern __shared__ float sm[];
    const int tid = threadIdx.x;
    const int wid = tid >> 5, lid = tid & 31;
    const int g = lid >> 2, t = lid & 3;
    const int m0 = blockIdx.x * 128;
    const int n0 = blockIdx.y * 128;
    const int m0w = (wid >> 1) * 32;          // warp M offset (4 warps in M)
    const int n0w = (wid & 1) * 64;           // warp N offset (2 warps in N)

    float acc[2][8][4];
#pragma unroll
    for (int mi = 0; mi < 2; mi++)
#pragma unroll
        for (int ni = 0; ni < 8; ni++)
#pragma unroll
            for (int q = 0; q < 4; q++) acc[mi][ni][q] = 0.0f;

    // cp.async staging addresses: per thread 4 segments per tile
    const int srow = tid >> 3;        // 0..31 (x4 iters -> 128 rows)
    const int sseg = tid & 7;         // 16B segment within 128B row

    auto issue = [&](int ch, int buf) {
        const int k0 = ch * 32;
        float* base = sm + buf * BUF_F;
        uint32_t aA = smem_u32(base)            + (uint32_t)(srow * PAD + sseg * 4) * 4u;
        uint32_t aH = smem_u32(base + TILE_F)   + (uint32_t)(srow * PAD + sseg * 4) * 4u;
        uint32_t aL = smem_u32(base + 2*TILE_F) + (uint32_t)(srow * PAD + sseg * 4) * 4u;
        const uint32_t rstep = 32u * PAD * 4u;
#pragma unroll
        for (int i = 0; i < 4; i++) {
            int r = srow + i * 32;
            cpa16(aA + i * rstep, &A [(size_t)(m0 + r) * lda + k0 + sseg * 4]);
            cpa16(aH + i * rstep, &Bh[(size_t)(n0 + r) * ldk + k0 + sseg * 4]);
            cpa16(aL + i * rstep, &Bl[(size_t)(n0 + r) * ldk + k0 + sseg * 4]);
        }
        CPA_COMMIT();
    };

    issue(0, 0);

    for (int ch = 0; ch < kchunks; ch++) {
        if (ch + 1 < kchunks) {
            issue(ch + 1, (ch + 1) & 1);
            asm volatile("cp.async.wait_group 1;" ::: "memory");
        } else {
            asm volatile("cp.async.wait_group 0;" ::: "memory");
        }
        __syncthreads();

        const float* As  = sm + (ch & 1) * BUF_F;
        const float* Bhs = As + TILE_F;
        const float* Bls = As + 2 * TILE_F;

#pragma unroll
        for (int kk = 0; kk < 32; kk += 8) {
            uint32_t ah[2][4], al[2][4];
#pragma unroll
            for (int mi = 0; mi < 2; mi++) {
                int r0 = (m0w + mi * 16 + g) * PAD + kk + t;
                float x0 = As[r0];
                float x1 = As[r0 + 8 * PAD];
                float x2 = As[r0 + 4];
                float x3 = As[r0 + 8 * PAD + 4];
                ah[mi][0] = f2tf(x0); al[mi][0] = f2tf(x0 - __uint_as_float(ah[mi][0]));
                ah[mi][1] = f2tf(x1); al[mi][1] = f2tf(x1 - __uint_as_float(ah[mi][1]));
                ah[mi][2] = f2tf(x2); al[mi][2] = f2tf(x2 - __uint_as_float(ah[mi][2]));
                ah[mi][3] = f2tf(x3); al[mi][3] = f2tf(x3 - __uint_as_float(ah[mi][3]));
            }
#pragma unroll
            for (int ni = 0; ni < 8; ni++) {
                int rn = (n0w + ni * 8 + g) * PAD + kk + t;
                uint32_t bh0 = __float_as_uint(Bhs[rn]);
                uint32_t bh1 = __float_as_uint(Bhs[rn + 4]);
                uint32_t bl0 = __float_as_uint(Bls[rn]);
                uint32_t bl1 = __float_as_uint(Bls[rn + 4]);
#pragma unroll
                for (int mi = 0; mi < 2; mi++) {
                    mma_tf32(acc[mi][ni], ah[mi], bh0, bh1);   // hi*hi
                    mma_tf32(acc[mi][ni], ah[mi], bl0, bl1);   // hi*lo
                    mma_tf32(acc[mi][ni], al[mi], bh0, bh1);   // lo*hi
                }
            }
        }
        __syncthreads();
    }

    // epilogue: frag (mi,ni): rows m0+m0w+mi*16+{g, g+8}, cols n0+n0w+ni*8+2t(+1)
#pragma unroll
    for (int mi = 0; mi < 2; mi++) {
        int row = m0 + m0w + mi * 16 + g;
#pragma unroll
        for (int ni = 0; ni < 8; ni++) {
            int col = n0 + n0w + ni * 8 + 2 * t;
            float b0 = bias[col], b1 = bias[col + 1];
            float v0 = acc[mi][ni][0] + b0;
            float v1 = acc[mi][ni][1] + b1;
            float v2 = acc[mi][ni][2] + b0;
            float v3 = acc[mi][ni][3] + b1;
            if (RELU) {
                v0 = fmaxf(v0, 0.f); v1 = fmaxf(v1, 0.f);
                v2 = fmaxf(v2, 0.f); v3 = fmaxf(v3, 0.f);
            }
            C[(size_t)row * ldc + col]           = v0;
            C[(size_t)row * ldc + col + 1]       = v1;
            C[(size_t)(row + 8) * ldc + col]     = v2;
            C[(size_t)(row + 8) * ldc + col + 1] = v3;
        }
    }
}

// ---------------- launch -----------------------------------------------------
extern "C" void kernel_launch(void* const* d_in, const int* in_sizes, int n_in,
                              void* d_out, int out_size) {
    const float* pts   = (const float*)d_in[0];
    const float* kp    = (const float*)d_in[1];
    const float* trans = (const float*)d_in[2];
    const int*   nbr   = (const int*)  d_in[3];
    const float* rest  = (const float*)d_in[4];
    const float* lat   = (const float*)d_in[5];
    const float* W1    = (const float*)d_in[6];
    const float* b1    = (const float*)d_in[7];
    const float* W2    = (const float*)d_in[8];
    const float* b2    = (const float*)d_in[9];
    const float* W3    = (const float*)d_in[10];
    const float* b3    = (const float*)d_in[11];
    float*       out   = (float*)d_out;

    void *pF, *pH1, *pH2, *p1h, *p1l, *p2h, *p2l, *p3h, *p3l;
    cudaGetSymbolAddress(&pF,  g_feat);
    cudaGetSymbolAddress(&pH1, g_h1);
    cudaGetSymbolAddress(&pH2, g_h2);
    cudaGetSymbolAddress(&p1h, g_W1h);
    cudaGetSymbolAddress(&p1l, g_W1l);
    cudaGetSymbolAddress(&p2h, g_W2h);
    cudaGetSymbolAddress(&p2l, g_W2l);
    cudaGetSymbolAddress(&p3h, g_W3h);
    cudaGetSymbolAddress(&p3l, g_W3l);
    float* F   = (float*)pF;
    float* H1  = (float*)pH1;
    float* H2  = (float*)pH2;

    cudaFuncSetAttribute((const void*)gemm_mma<true >, cudaFuncAttributeMaxDynamicSharedMemorySize, GEMM_SMEM);
    cudaFuncSetAttribute((const void*)gemm_mma<false>, cudaFuncAttributeMaxDynamicSharedMemorySize, GEMM_SMEM);

    invert_kernel<<<(NV + 127) / 128, 128>>>(trans);
    knn_kernel<<<dim3(NPTS / 256, SPLIT), 256>>>(pts, kp);
    knn_reduce<<<NPTS / 256, 256>>>();
    feat_kernel<<<NPTS / 8, 256>>>(pts, kp, nbr, rest, lat, out);

    transpose_split<<<dim3(LDF / 32, 8), dim3(32, 8)>>>(W1, 700, (float*)p1h, (float*)p1l, LDF);
    transpose_split<<<dim3(256 / 32, 8), dim3(32, 8)>>>(W2, 256, (float*)p2h, (float*)p2l, 256);
    transpose_split<<<dim3(256 / 32, 8), dim3(32, 8)>>>(W3, 256, (float*)p3h, (float*)p3l, 256);

    gemm_mma<true ><<<dim3(NPTS / 128, 2), 256, GEMM_SMEM>>>(F,  LDF, (float*)p1h, (float*)p1l, LDF, b1, H1,  256, LDF / 32);
    gemm_mma<true ><<<dim3(NPTS / 128, 2), 256, GEMM_SMEM>>>(H1, 256, (float*)p2h, (float*)p2l, 256, b2, H2,  256, 256 / 32);
    gemm_mma<false><<<dim3(NPTS / 128, 2), 256, GEMM_SMEM>>>(H2, 256, (float*)p3h, (float*)p3l, 256, b3, out, 283, 256 / 32);
}

// round 4
// speedup vs baseline: 3.9168x; 1.4651x over previous
#include <cuda_runtime.h>
#include <cuda_fp16.h>
#include <cstdint>
#include <math.h>

#define NV      6890
#define NPTS    16384
#define SPLIT   4
#define KRANGE  1723     // ceil(6890/4)
#define LDF     704      // padded feature leading dim (700 -> 704)

// ---------------- scratch (device globals; no allocations allowed) ----------
__device__ __align__(16) __half  g_featH[(size_t)NPTS * LDF];
__device__ __align__(16) __half  g_featL[(size_t)NPTS * LDF];
__device__ __align__(16) __half  g_h1H[(size_t)NPTS * 256];
__device__ __align__(16) __half  g_h1L[(size_t)NPTS * 256];
__device__ __align__(16) __half  g_h2H[(size_t)NPTS * 256];
__device__ __align__(16) __half  g_h2L[(size_t)NPTS * 256];
__device__ __align__(16) __half  g_W1h[(size_t)256 * LDF];
__device__ __align__(16) __half  g_W1l[(size_t)256 * LDF];
__device__ __align__(16) __half  g_W2h[(size_t)256 * 256];
__device__ __align__(16) __half  g_W2l[(size_t)256 * 256];
__device__ __align__(16) __half  g_W3h[(size_t)256 * 256];
__device__ __align__(16) __half  g_W3l[(size_t)256 * 256];
__device__ float                 g_Rinv[NV * 9];
__device__ int                   g_knn[NPTS];
__device__ unsigned long long    g_part[SPLIT * NPTS];

// ======================= small PTX helpers ===================================
__device__ __forceinline__ uint32_t smem_u32(const void* p) {
    uint32_t a;
    asm("{ .reg .u64 t; cvta.to.shared.u64 t, %1; cvt.u32.u64 %0, t; }" : "=r"(a) : "l"(p));
    return a;
}
__device__ __forceinline__ void cpa16(uint32_t dst, const void* src) {
    asm volatile("cp.async.cg.shared.global [%0], [%1], 16;" :: "r"(dst), "l"(src));
}
#define CPA_COMMIT() asm volatile("cp.async.commit_group;" ::: "memory")

__device__ __forceinline__ void ldm4(uint32_t* r, uint32_t addr) {
    asm volatile("ldmatrix.sync.aligned.m8n8.x4.shared.b16 {%0,%1,%2,%3}, [%4];"
                 : "=r"(r[0]), "=r"(r[1]), "=r"(r[2]), "=r"(r[3]) : "r"(addr));
}
__device__ __forceinline__ void mma16816(float* c, const uint32_t* a, uint32_t b0, uint32_t b1) {
    asm volatile(
        "mma.sync.aligned.m16n8k16.row.col.f32.f16.f16.f32 "
        "{%0,%1,%2,%3}, {%4,%5,%6,%7}, {%8,%9}, {%0,%1,%2,%3};"
        : "+f"(c[0]), "+f"(c[1]), "+f"(c[2]), "+f"(c[3])
        : "r"(a[0]), "r"(a[1]), "r"(a[2]), "r"(a[3]), "r"(b0), "r"(b1));
}

// write fp32 value as fp16 hi/lo pair
__device__ __forceinline__ void wsplit(__half* H, __half* L, size_t idx, float v) {
    __half h = __float2half_rn(v);
    H[idx] = h;
    L[idx] = __float2half_rn(v - __half2float(h));
}

// ---------------- accurate-enough fp32 sincos (no FP64) ---------------------
__device__ __forceinline__ void sincos_acc(float x, float* s, float* c) {
    const float C1 = 6.28125f;
    const float C2 = (float)1.9353071795864769e-3;
    const float C3 = (float)(6.283185307179586476925286766559 - 6.28125 -
                             (double)((float)1.9353071795864769e-3));
    float q = rintf(x * 0.15915494309189535f);
    float r = fmaf(q, -C1, x);
    r = fmaf(q, -C2, r);
    r = fmaf(q, -C3, r);
    sincosf(r, s, c);
}

// ---------------- kernel 1: per-vertex inverse of 4x4, keep top-left 3x3 ----
__global__ void invert_kernel(const float* __restrict__ trans) {
    int v = blockIdx.x * blockDim.x + threadIdx.x;
    if (v >= NV) return;
    float m[16];
#pragma unroll
    for (int k = 0; k < 16; k++) m[k] = trans[k * NV + v];

    float i0  =  m[5]*m[10]*m[15] - m[5]*m[11]*m[14] - m[9]*m[6]*m[15] + m[9]*m[7]*m[14] + m[13]*m[6]*m[11] - m[13]*m[7]*m[10];
    float i4  = -m[4]*m[10]*m[15] + m[4]*m[11]*m[14] + m[8]*m[6]*m[15] - m[8]*m[7]*m[14] - m[12]*m[6]*m[11] + m[12]*m[7]*m[10];
    float i8  =  m[4]*m[9]*m[15]  - m[4]*m[11]*m[13] - m[8]*m[5]*m[15] + m[8]*m[7]*m[13] + m[12]*m[5]*m[11] - m[12]*m[7]*m[9];
    float i12 = -m[4]*m[9]*m[14]  + m[4]*m[10]*m[13] + m[8]*m[5]*m[14] - m[8]*m[6]*m[13] - m[12]*m[5]*m[10] + m[12]*m[6]*m[9];
    float i1  = -m[1]*m[10]*m[15] + m[1]*m[11]*m[14] + m[9]*m[2]*m[15] - m[9]*m[3]*m[14] - m[13]*m[2]*m[11] + m[13]*m[3]*m[10];
    float i5  =  m[0]*m[10]*m[15] - m[0]*m[11]*m[14] - m[8]*m[2]*m[15] + m[8]*m[3]*m[14] + m[12]*m[2]*m[11] - m[12]*m[3]*m[10];
    float i9  = -m[0]*m[9]*m[15]  + m[0]*m[11]*m[13] + m[8]*m[1]*m[15] - m[8]*m[3]*m[13] - m[12]*m[1]*m[11] + m[12]*m[3]*m[9];
    float i2  =  m[1]*m[6]*m[15]  - m[1]*m[7]*m[14]  - m[5]*m[2]*m[15] + m[5]*m[3]*m[14] + m[13]*m[2]*m[7]  - m[13]*m[3]*m[6];
    float i6  = -m[0]*m[6]*m[15]  + m[0]*m[7]*m[14]  + m[4]*m[2]*m[15] - m[4]*m[3]*m[14] - m[12]*m[2]*m[7]  + m[12]*m[3]*m[6];
    float i10 =  m[0]*m[5]*m[15]  - m[0]*m[7]*m[13]  - m[4]*m[1]*m[15] + m[4]*m[3]*m[13] + m[12]*m[1]*m[7]  - m[12]*m[3]*m[5];

    float det = m[0]*i0 + m[1]*i4 + m[2]*i8 + m[3]*i12;
    float id  = 1.0f / det;
    float* R = g_Rinv + v * 9;
    R[0] = i0*id;  R[1] = i1*id;  R[2] = i2*id;
    R[3] = i4*id;  R[4] = i5*id;  R[5] = i6*id;
    R[6] = i8*id;  R[7] = i9*id;  R[8] = i10*id;
}

// ---------------- kernel 2: KNN, 4-way keypoint split ------------------------
__global__ __launch_bounds__(256) void knn_kernel(const float* __restrict__ pts,
                                                  const float* __restrict__ kp) {
    __shared__ float4 sk[KRANGE];
    int pt = blockIdx.x * 256 + threadIdx.x;
    int ks = blockIdx.y * KRANGE;
    int ke = min(ks + KRANGE, NV);
    int n  = ke - ks;

    for (int i = threadIdx.x; i < n; i += 256) {
        int vv = ks + i;
        float kx = kp[vv*3], ky = kp[vv*3+1], kz = kp[vv*3+2];
        sk[i] = make_float4(kx, ky, kz, -0.5f*(kx*kx + ky*ky + kz*kz));
    }
    __syncthreads();

    float px = pts[pt*6], py = pts[pt*6+1], pz = pts[pt*6+2];
    float best = -1e30f; int bi = ks;

    int i = 0;
#pragma unroll 1
    for (; i + 4 <= n; i += 4) {
#pragma unroll
        for (int u = 0; u < 4; u++) {
            float4 k = sk[i+u];
            float s = fmaf(px, k.x, fmaf(py, k.y, fmaf(pz, k.z, k.w)));
            if (s > best) { best = s; bi = ks + i + u; }
        }
    }
    for (; i < n; i++) {
        float4 k = sk[i];
        float s = fmaf(px, k.x, fmaf(py, k.y, fmaf(pz, k.z, k.w)));
        if (s > best) { best = s; bi = ks + i; }
    }
    float mneg = -best;
    unsigned int ub = __float_as_uint(mneg);
    ub = (ub & 0x80000000u) ? ~ub : (ub | 0x80000000u);
    g_part[blockIdx.y * NPTS + pt] = ((unsigned long long)ub << 32) | (unsigned int)bi;
}

__global__ void knn_reduce() {
    int pt = blockIdx.x * blockDim.x + threadIdx.x;
    if (pt >= NPTS) return;
    unsigned long long b = g_part[pt];
#pragma unroll
    for (int s = 1; s < SPLIT; s++) {
        unsigned long long o = g_part[s * NPTS + pt];
        if (o < b) b = o;
    }
    g_knn[pt] = (int)(b & 0xFFFFFFFFull);
}

// ---------------- kernel 3: feature build (split fp16) + direction posenc ---
__global__ __launch_bounds__(256) void feat_kernel(const float* __restrict__ pts,
                                                   const float* __restrict__ kp,
                                                   const int*   __restrict__ nbr,
                                                   const float* __restrict__ rest,
                                                   const float* __restrict__ lat,
                                                   float*       __restrict__ out) {
    int gw   = (blockIdx.x * blockDim.x + threadIdx.x) >> 5;
    int lane = threadIdx.x & 31;
    if (gw >= NPTS) return;

    float px = pts[gw*6], py = pts[gw*6+1], pz = pts[gw*6+2];
    int kidx = g_knn[gw];

    int vj = (lane < 7) ? nbr[kidx*7 + lane] : 0;
    int j  = (lane < 21) ? (lane / 3) : ((lane < 28) ? (lane - 21) : 0);
    int v  = __shfl_sync(0xffffffffu, vj, j);

    float vf = 0.0f;
    if (lane < 21) {
        vf = rest[v*3 + (lane % 3)];
    } else if (lane < 28) {
        float dx = px - kp[v*3], dy = py - kp[v*3+1], dz = pz - kp[v*3+2];
        vf = sqrtf(dx*dx + dy*dy + dz*dz);
    }

    size_t base = (size_t)gw * LDF;
    if (lane < 28) {
        wsplit(g_featH, g_featL, base + lane, vf);
        float freq = 1.0f;
#pragma unroll
        for (int k = 0; k < 10; k++) {
            float s, c;
            sincos_acc(vf * freq, &s, &c);
            wsplit(g_featH, g_featL, base + 28  + k*28 + lane, s);
            wsplit(g_featH, g_featL, base + 308 + k*28 + lane, c);
            freq *= 2.0f;
        }
    }
    if (lane < 4) {
        g_featH[base + 700 + lane] = __float2half_rn(0.0f);
        g_featL[base + 700 + lane] = __float2half_rn(0.0f);
    }

#pragma unroll
    for (int it = 0; it < 4; it++) {
        int l  = it * 32 + lane;
        int jj = (l < 112) ? (l >> 4) : 0;
        int vv = __shfl_sync(0xffffffffu, vj, jj);
        if (l < 112) wsplit(g_featH, g_featL, base + 588 + l, lat[vv*16 + (l & 15)]);
    }

    if (lane == 0) {
        float dx = px - kp[kidx*3], dy = py - kp[kidx*3+1], dz = pz - kp[kidx*3+2];
        const float* R = g_Rinv + kidx * 9;
        float d0 = R[0]*dx + R[1]*dy + R[2]*dz;
        float d1 = R[3]*dx + R[4]*dy + R[5]*dz;
        float d2 = R[6]*dx + R[7]*dy + R[8]*dz;
        float nn = sqrtf(d0*d0 + d1*d1 + d2*d2);
        float iv = 1.0f / fmaxf(nn, 1e-12f);
        d0 *= iv; d1 *= iv; d2 *= iv;
        float* op = out + (size_t)gw * 283 + 256;
        op[0] = d0; op[1] = d1; op[2] = d2;
        float dir[3] = {d0, d1, d2};
        float freq = 1.0f;
#pragma unroll
        for (int k = 0; k < 4; k++) {
#pragma unroll
            for (int c = 0; c < 3; c++) {
                float s, cc;
                sincos_acc(dir[c] * freq, &s, &cc);
                op[3  + k*3 + c] = s;
                op[15 + k*3 + c] = cc;
            }
            freq *= 2.0f;
        }
    }
}

// ---------- weight transpose + fp16 hi/lo split: W[K][256] -> Wh/Wl[256][ldk]
__global__ void transpose_split(const float* __restrict__ W, int K,
                                __half* __restrict__ Wh, __half* __restrict__ Wl, int ldk) {
    __shared__ float tile[32][33];
    int kb = blockIdx.x * 32;
    int nb = blockIdx.y * 32;
    int tx = threadIdx.x, ty = threadIdx.y;   // 32 x 8
#pragma unroll
    for (int i = 0; i < 4; i++) {
        int k = kb + ty + i * 8;
        tile[ty + i * 8][tx] = (k < K) ? W[(size_t)k * 256 + nb + tx] : 0.0f;
    }
    __syncthreads();
#pragma unroll
    for (int i = 0; i < 4; i++) {
        int n = nb + ty + i * 8;
        float v = tile[tx][ty + i * 8];
        wsplit(Wh, Wl, (size_t)n * ldk + kb + tx, v);
    }
}

// ---------------- kernel 4: fp16 3x-split HMMA GEMM -------------------------
// C[M,256] = act(A[M,K] @ Wt[256,K]^T + bias), CTA tile 128x128, 8 warps 4x2.
// Operands pre-split into fp16 hi/lo. Smem rows padded to 40 halves (80 B):
// ldmatrix phases hit all 32 banks exactly once (conflict-free).
#define PADH   40
#define TILEB  (128 * PADH * 2)            // 10240 B per tile
#define BUFB   (4 * TILEB)                 // Ah, Al, Bh, Bl
#define GEMM_SMEM (2 * BUFB)               // 81920 B

// OUTMODE 0: fp32 store (no relu). OUTMODE 1: relu + split fp16 hi/lo store.
template <int OUTMODE>
__global__ __launch_bounds__(256, 2) void gemm_hmma(
    const __half* __restrict__ Ah, const __half* __restrict__ Al, int lda,
    const __half* __restrict__ Bh, const __half* __restrict__ Bl, int ldb,
    const float* __restrict__ bias,
    float* __restrict__ Cf, int ldc,
    __half* __restrict__ ChH, __half* __restrict__ ChL,
    int kchunks)
{
    extern __shared__ char sm[];
    const int tid  = threadIdx.x;
    const int wid  = tid >> 5, lane = tid & 31;
    const int g    = lane >> 2, t = lane & 3;
    const int m0   = blockIdx.x * 128, n0 = blockIdx.y * 128;
    const int m0w  = (wid >> 1) * 32, n0w = (wid & 1) * 64;

    float acc[2][8][4];
#pragma unroll
    for (int mi = 0; mi < 2; mi++)
#pragma unroll
        for (int ni = 0; ni < 8; ni++)
#pragma unroll
            for (int q = 0; q < 4; q++) acc[mi][ni][q] = 0.0f;

    auto issue = [&](int ch, int buf) {
        const int k0 = ch * 32;
        char* base = sm + buf * BUFB;
#pragma unroll
        for (int i = 0; i < 2; i++) {
            int s = tid + i * 256;                 // 0..511
            int r = s >> 2, c = (s & 3) * 8;       // row, 8-half (16B) segment
            uint32_t off = (uint32_t)(r * PADH + c) * 2;
            cpa16(smem_u32(base)             + off, Ah + (size_t)(m0 + r) * lda + k0 + c);
            cpa16(smem_u32(base + TILEB)     + off, Al + (size_t)(m0 + r) * lda + k0 + c);
            cpa16(smem_u32(base + 2 * TILEB) + off, Bh + (size_t)(n0 + r) * ldb + k0 + c);
            cpa16(smem_u32(base + 3 * TILEB) + off, Bl + (size_t)(n0 + r) * ldb + k0 + c);
        }
        CPA_COMMIT();
    };

    issue(0, 0);

    for (int ch = 0; ch < kchunks; ch++) {
        if (ch + 1 < kchunks) {
            issue(ch + 1, (ch + 1) & 1);
            asm volatile("cp.async.wait_group 1;" ::: "memory");
        } else {
            asm volatile("cp.async.wait_group 0;" ::: "memory");
        }
        __syncthreads();

        char* base = sm + (ch & 1) * BUFB;
        uint32_t sAh = smem_u32(base);
        uint32_t sAl = sAh + TILEB;
        uint32_t sBh = sAh + 2 * TILEB;
        uint32_t sBl = sAh + 3 * TILEB;

        const int arow = lane & 15;
        const int asel = (lane >> 4) << 3;              // +8 halves for tiles 2,3
        const int brow = (lane & 7) + ((lane & 16) ? 8 : 0);
        const int bsel = (lane & 8) ? 8 : 0;

#pragma unroll
        for (int ks = 0; ks < 2; ks++) {
            const int kc = ks * 16;
            uint32_t ah[2][4], al[2][4];
#pragma unroll
            for (int mi = 0; mi < 2; mi++) {
                uint32_t off = (uint32_t)((m0w + mi * 16 + arow) * PADH + kc + asel) * 2;
                ldm4(ah[mi], sAh + off);
                ldm4(al[mi], sAl + off);
            }
#pragma unroll
            for (int p = 0; p < 4; p++) {
                uint32_t bh[4], bl[4];
                uint32_t off = (uint32_t)((n0w + p * 16 + brow) * PADH + kc + bsel) * 2;
                ldm4(bh, sBh + off);
                ldm4(bl, sBl + off);
#pragma unroll
                for (int q = 0; q < 2; q++) {
#pragma unroll
                    for (int mi = 0; mi < 2; mi++) {
                        float* c = acc[mi][p * 2 + q];
                        mma16816(c, ah[mi], bh[q * 2], bh[q * 2 + 1]);   // hi*hi
                        mma16816(c, ah[mi], bl[q * 2], bl[q * 2 + 1]);   // hi*lo
                        mma16816(c, al[mi], bh[q * 2], bh[q * 2 + 1]);   // lo*hi
                    }
                }
            }
        }
        __syncthreads();
    }

    // epilogue: frag (mi,ni): rows row, row+8; cols col, col+1
#pragma unroll
    for (int mi = 0; mi < 2; mi++) {
        int row = m0 + m0w + mi * 16 + g;
#pragma unroll
        for (int ni = 0; ni < 8; ni++) {
            int col = n0 + n0w + ni * 8 + 2 * t;
            float b0 = bias[col], b1 = bias[col + 1];
            float v0 = acc[mi][ni][0] + b0;
            float v1 = acc[mi][ni][1] + b1;
            float v2 = acc[mi][ni][2] + b0;
            float v3 = acc[mi][ni][3] + b1;
            if (OUTMODE == 1) {
                v0 = fmaxf(v0, 0.f); v1 = fmaxf(v1, 0.f);
                v2 = fmaxf(v2, 0.f); v3 = fmaxf(v3, 0.f);
                __half h0 = __float2half_rn(v0), h1 = __float2half_rn(v1);
                __half h2 = __float2half_rn(v2), h3 = __float2half_rn(v3);
                __half l0 = __float2half_rn(v0 - __half2float(h0));
                __half l1 = __float2half_rn(v1 - __half2float(h1));
                __half l2 = __float2half_rn(v2 - __half2float(h2));
                __half l3 = __float2half_rn(v3 - __half2float(h3));
                *(__half2*)&ChH[(size_t)row * 256 + col]       = __halves2half2(h0, h1);
                *(__half2*)&ChL[(size_t)row * 256 + col]       = __halves2half2(l0, l1);
                *(__half2*)&ChH[(size_t)(row + 8) * 256 + col] = __halves2half2(h2, h3);
                *(__half2*)&ChL[(size_t)(row + 8) * 256 + col] = __halves2half2(l2, l3);
            } else {
                Cf[(size_t)row * ldc + col]           = v0;
                Cf[(size_t)row * ldc + col + 1]       = v1;
                Cf[(size_t)(row + 8) * ldc + col]     = v2;
                Cf[(size_t)(row + 8) * ldc + col + 1] = v3;
            }
        }
    }
}

// ---------------- launch -----------------------------------------------------
extern "C" void kernel_launch(void* const* d_in, const int* in_sizes, int n_in,
                              void* d_out, int out_size) {
    const float* pts   = (const float*)d_in[0];
    const float* kp    = (const float*)d_in[1];
    const float* trans = (const float*)d_in[2];
    const int*   nbr   = (const int*)  d_in[3];
    const float* rest  = (const float*)d_in[4];
    const float* lat   = (const float*)d_in[5];
    const float* W1    = (const float*)d_in[6];
    const float* b1    = (const float*)d_in[7];
    const float* W2    = (const float*)d_in[8];
    const float* b2    = (const float*)d_in[9];
    const float* W3    = (const float*)d_in[10];
    const float* b3    = (const float*)d_in[11];
    float*       out   = (float*)d_out;

    void *pFH, *pFL, *p1H, *p1L, *p2H, *p2L;
    void *w1h, *w1l, *w2h, *w2l, *w3h, *w3l;
    cudaGetSymbolAddress(&pFH, g_featH);
    cudaGetSymbolAddress(&pFL, g_featL);
    cudaGetSymbolAddress(&p1H, g_h1H);
    cudaGetSymbolAddress(&p1L, g_h1L);
    cudaGetSymbolAddress(&p2H, g_h2H);
    cudaGetSymbolAddress(&p2L, g_h2L);
    cudaGetSymbolAddress(&w1h, g_W1h);
    cudaGetSymbolAddress(&w1l, g_W1l);
    cudaGetSymbolAddress(&w2h, g_W2h);
    cudaGetSymbolAddress(&w2l, g_W2l);
    cudaGetSymbolAddress(&w3h, g_W3h);
    cudaGetSymbolAddress(&w3l, g_W3l);

    cudaFuncSetAttribute((const void*)gemm_hmma<0>, cudaFuncAttributeMaxDynamicSharedMemorySize, GEMM_SMEM);
    cudaFuncSetAttribute((const void*)gemm_hmma<1>, cudaFuncAttributeMaxDynamicSharedMemorySize, GEMM_SMEM);

    invert_kernel<<<(NV + 127) / 128, 128>>>(trans);
    knn_kernel<<<dim3(NPTS / 256, SPLIT), 256>>>(pts, kp);
    knn_reduce<<<NPTS / 256, 256>>>();
    feat_kernel<<<NPTS / 8, 256>>>(pts, kp, nbr, rest, lat, out);

    transpose_split<<<dim3(LDF / 32, 8), dim3(32, 8)>>>(W1, 700, (__half*)w1h, (__half*)w1l, LDF);
    transpose_split<<<dim3(256 / 32, 8), dim3(32, 8)>>>(W2, 256, (__half*)w2h, (__half*)w2l, 256);
    transpose_split<<<dim3(256 / 32, 8), dim3(32, 8)>>>(W3, 256, (__half*)w3h, (__half*)w3l, 256);

    dim3 ggrid(NPTS / 128, 2);
    gemm_hmma<1><<<ggrid, 256, GEMM_SMEM>>>(
        (const __half*)pFH, (const __half*)pFL, LDF,
        (const __half*)w1h, (const __half*)w1l, LDF,
        b1, nullptr, 0, (__half*)p1H, (__half*)p1L, LDF / 32);
    gemm_hmma<1><<<ggrid, 256, GEMM_SMEM>>>(
        (const __half*)p1H, (const __half*)p1L, 256,
        (const __half*)w2h, (const __half*)w2l, 256,
        b2, nullptr, 0, (__half*)p2H, (__half*)p2L, 256 / 32);
    gemm_hmma<0><<<ggrid, 256, GEMM_SMEM>>>(
        (const __half*)p2H, (const __half*)p2L, 256,
        (const __half*)w3h, (const __half*)w3l, 256,
        b3, out, 283, nullptr, nullptr, 256 / 32);
}